// round 15
// baseline (speedup 1.0000x reference)
#include <cuda_runtime.h>
#include <cuda_fp16.h>
#include <math.h>

#define NN 50000
#define NE 800000

__device__ float  g_h [NN*64];
__device__ float  g_p0[NN*64];
__device__ float  g_q0[NN*64];
__device__ float  g_p1[NN*64];
__device__ float  g_q1[NN*64];
__device__ float  g_ft [NN*64];
__device__ float  g_ft2[NN*64];
__device__ __half g_h3[(size_t)NE*64];
__device__ float  g_s [NE*2];
__device__ int    g_count [NN];
__device__ int    g_off   [NN];
__device__ int    g_cursor[NN];
__device__ int    g_perm  [NE];

__device__ __forceinline__ float ftanh(float x){
    float e = __expf(2.0f*x);
    return 1.0f - __fdividef(2.0f, e + 1.0f);
}
__device__ __forceinline__ float fsigm(float x){
    return __fdividef(1.0f, 1.0f + __expf(-x));
}

#define KK_COMP(v,kk) ((kk)==0?(v).x:((kk)==1?(v).y:((kk)==2?(v).z:(v).w)))
#define ROW_FMA8(ar, va) do{ \
  ar[0] += (va)*w0.x; ar[1] += (va)*w0.y; ar[2] += (va)*w0.z; ar[3] += (va)*w0.w; \
  ar[4] += (va)*w1.x; ar[5] += (va)*w1.y; ar[6] += (va)*w1.z; ar[7] += (va)*w1.w; }while(0)

__device__ __forceinline__ void gemm2x8(const float (*A)[68], const float (*W)[68],
                                        int rr, int c0, float acc[2][8]){
  #pragma unroll
  for (int k = 0; k < 64; k += 4){
    float4 a0 = *(const float4*)&A[rr+0][k];
    float4 a1 = *(const float4*)&A[rr+1][k];
    #pragma unroll
    for (int kk = 0; kk < 4; kk++){
      float4 w0 = *(const float4*)&W[k+kk][c0];
      float4 w1 = *(const float4*)&W[k+kk][c0+4];
      float va0 = KK_COMP(a0,kk), va1 = KK_COMP(a1,kk);
      ROW_FMA8(acc[0], va0); ROW_FMA8(acc[1], va1);
    }
  }
}

// tf32 m16n8k8 mma, fp32 accumulate
__device__ __forceinline__ void mma_tf32(float c[4], unsigned a0, unsigned a1,
                                         unsigned a2, unsigned a3,
                                         unsigned b0, unsigned b1){
  asm("mma.sync.aligned.m16n8k8.row.col.f32.tf32.tf32.f32 "
      "{%0,%1,%2,%3}, {%4,%5,%6,%7}, {%8,%9}, {%0,%1,%2,%3};"
      : "+f"(c[0]), "+f"(c[1]), "+f"(c[2]), "+f"(c[3])
      : "r"(a0), "r"(a1), "r"(a2), "r"(a3), "r"(b0), "r"(b1));
}

__global__ void k_zero(){
  int i = blockIdx.x*256 + threadIdx.x;
  if (i < NN) g_count[i] = 0;
}
__global__ void k_hist(const int* __restrict__ dst){
  int e = blockIdx.x*256 + threadIdx.x;
  if (e < NE) atomicAdd(&g_count[dst[e]], 1);
}
__global__ void __launch_bounds__(1024) k_scan(){
  __shared__ int wsum[32];
  __shared__ int carry_s;
  int t = threadIdx.x, lane = t & 31, wid = t >> 5;
  if (t == 0) carry_s = 0;
  __syncthreads();
  for (int c = 0; c < NN; c += 1024){
    int i = c + t;
    int v = (i < NN) ? g_count[i] : 0;
    int s = v;
    #pragma unroll
    for (int o = 1; o < 32; o <<= 1){
      int n = __shfl_up_sync(0xffffffffu, s, o);
      if (lane >= o) s += n;
    }
    if (lane == 31) wsum[wid] = s;
    __syncthreads();
    if (wid == 0){
      int ws = wsum[lane];
      #pragma unroll
      for (int o = 1; o < 32; o <<= 1){
        int n = __shfl_up_sync(0xffffffffu, ws, o);
        if (lane >= o) ws += n;
      }
      wsum[lane] = ws;
    }
    __syncthreads();
    int carry = carry_s;
    int excl = s - v + (wid ? wsum[wid-1] : 0) + carry;
    if (i < NN){ g_off[i] = excl; g_cursor[i] = excl; }
    int total = wsum[31];
    __syncthreads();
    if (t == 0) carry_s = carry + total;
    __syncthreads();
  }
}
__global__ void k_scatter(const int* __restrict__ dst){
  int e = blockIdx.x*256 + threadIdx.x;
  if (e < NE){
    int d = dst[e];
    int pos = atomicAdd(&g_cursor[d], 1);
    g_perm[pos] = e;
  }
}

// Fused node kernel (R12)
__global__ void __launch_bounds__(256) k_node(
    const float* __restrict__ x, const float* __restrict__ W_lin, const float* __restrict__ b_lin,
    const float* __restrict__ Wx0, const float* __restrict__ Wh0, const float* __restrict__ b0,
    const float* __restrict__ Wx1, const float* __restrict__ Wh1, const float* __restrict__ b1){
  extern __shared__ float sm[];
  float (*Xs)[68] = (float(*)[68])sm;
  float (*Ws)[68] = (float(*)[68])(sm + 64*68);
  float (*Ts)[68] = (float(*)[68])(sm + 2*64*68);
  int t = threadIdx.x;
  int r0 = blockIdx.x * 64;
  #pragma unroll
  for (int j = 0; j < 4; j++){
    int idx = t + 256*j;
    int r = idx >> 4, c4 = (idx & 15) * 4;
    float4 v = make_float4(0.f,0.f,0.f,0.f);
    if (r0 + r < NN) v = *(const float4*)&x[(size_t)(r0+r)*64 + c4];
    *(float4*)&Xs[r][c4] = v;
    *(float4*)&Ws[r][c4] = *(const float4*)&W_lin[r*64 + c4];
  }
  __syncthreads();
  int cg = t & 7, eg = t >> 3;
  int c0 = cg * 8, rr = eg * 2;

  float hacc[2][8] = {};
  gemm2x8(Xs, Ws, rr, c0, hacc);
  float bv[8];
  *(float4*)&bv[0] = *(const float4*)&b_lin[c0];
  *(float4*)&bv[4] = *(const float4*)&b_lin[c0+4];
  float hval[2][8];
  #pragma unroll
  for (int i = 0; i < 2; i++){
    #pragma unroll
    for (int j = 0; j < 8; j++) hval[i][j] = hacc[i][j] + bv[j];
    int r = r0 + rr + i;
    if (r < NN){
      *(float4*)&g_h[(size_t)r*64 + c0]   = *(float4*)&hval[i][0];
      *(float4*)&g_h[(size_t)r*64 + c0+4] = *(float4*)&hval[i][4];
    }
  }
  __syncthreads();
  #pragma unroll
  for (int i = 0; i < 2; i++){
    *(float4*)&Xs[rr+i][c0]   = *(float4*)&hval[i][0];
    *(float4*)&Xs[rr+i][c0+4] = *(float4*)&hval[i][4];
  }

  for (int enc = 0; enc < 2; enc++){
    const float* Wx = enc ? Wx1 : Wx0;
    const float* Wh = enc ? Wh1 : Wh0;
    const float* bb = enc ? b1  : b0;
    float* gp = enc ? g_p1 : g_p0;
    float* gq = enc ? g_q1 : g_q0;
    __syncthreads();
    #pragma unroll
    for (int j = 0; j < 4; j++){
      int idx = t + 256*j;
      int r = idx >> 4, c4 = (idx & 15) * 4;
      *(float4*)&Ws[r][c4] = *(const float4*)&Wx[r*64 + c4];
    }
    __syncthreads();
    float acc[2][8] = {};
    gemm2x8(Xs, Ws, rr, c0, acc);
    *(float4*)&bv[0] = *(const float4*)&bb[c0];
    *(float4*)&bv[4] = *(const float4*)&bb[c0+4];
    #pragma unroll
    for (int i = 0; i < 2; i++){
      int r = r0 + rr + i;
      if (r < NN){
        *(float4*)&gp[(size_t)r*64 + c0]   = *(float4*)&acc[i][0];
        *(float4*)&gp[(size_t)r*64 + c0+4] = *(float4*)&acc[i][4];
      }
      #pragma unroll
      for (int j = 0; j < 8; j++) Ts[rr+i][c0+j] = ftanh(acc[i][j] + bv[j]);
    }
    __syncthreads();
    #pragma unroll
    for (int j = 0; j < 4; j++){
      int idx = t + 256*j;
      int r = idx >> 4, c4 = (idx & 15) * 4;
      *(float4*)&Ws[r][c4] = *(const float4*)&Wh[r*64 + c4];
    }
    __syncthreads();
    float acc2[2][8] = {};
    gemm2x8(Ts, Ws, rr, c0, acc2);
    #pragma unroll
    for (int i = 0; i < 2; i++){
      int r = r0 + rr + i;
      if (r < NN){
        *(float4*)&gq[(size_t)r*64 + c0]   = *(float4*)&acc2[i][0];
        *(float4*)&gq[(size_t)r*64 + c0+4] = *(float4*)&acc2[i][4];
      }
    }
  }
}

// Edge pass: M=32 per warp (two m16 tiles share each B fragment), 256 edges/block.
__global__ void __launch_bounds__(256, 2) k_edge1(
    const float* __restrict__ ef0, const float* __restrict__ ef1,
    const int* __restrict__ src, const int* __restrict__ dst,
    const float* __restrict__ Wx0, const float* __restrict__ Wh0, const float* __restrict__ b0,
    const float* __restrict__ Wx1, const float* __restrict__ Wh1, const float* __restrict__ b1,
    const float* __restrict__ attn0, const float* __restrict__ eta0,
    const float* __restrict__ attn1, const float* __restrict__ eta1,
    const float* __restrict__ delta)
{
  extern __shared__ float sm[];
  float (*As)[72] = (float(*)[72])sm;              // 256 x 72
  float (*W1)[72] = (float(*)[72])(sm + 256*72);   // Wx 64 x 72
  float (*W2)[72] = (float(*)[72])(sm + 320*72);   // Wh 64 x 72
  int* s_src = (int*)(sm + 384*72);
  int* s_dst = s_src + 256;

  int t = threadIdx.x;
  int ebase = blockIdx.x * 256;
  s_src[t] = src[ebase + t];
  s_dst[t] = dst[ebase + t];

  int w = t >> 5, lane = t & 31;
  int g = lane >> 2, tig = lane & 3;
  int r0 = w*32 + g;                    // thread's rows: r0, +8, +16, +24

  float edot[2][4][2];                  // [enc][rowslot][head]

  for (int enc = 0; enc < 2; enc++){
    const float* ef  = enc ? ef1  : ef0;
    const float* Wx  = enc ? Wx1  : Wx0;
    const float* Wh  = enc ? Wh1  : Wh0;
    const float* bb  = enc ? b1   : b0;
    const float* gq  = enc ? g_q1 : g_q0;
    const float* gp  = enc ? g_p1 : g_p0;
    const float* att = enc ? attn1 : attn0;

    __syncthreads();
    #pragma unroll
    for (int j = 0; j < 16; j++){
      int idx = t + 256*j;
      int e = idx >> 4, c4 = (idx & 15) * 4;
      *(float4*)&As[e][c4] = *(const float4*)&ef[(size_t)(ebase+e)*64 + c4];
    }
    #pragma unroll
    for (int j = 0; j < 4; j++){
      int idx = t + 256*j;
      int r = idx >> 4, c4 = (idx & 15) * 4;
      *(float4*)&W1[r][c4] = *(const float4*)&Wx[r*64 + c4];
      *(float4*)&W2[r][c4] = *(const float4*)&Wh[r*64 + c4];
    }
    __syncthreads();

    // ---- GEMM1: ef @ Wx (two m16 tiles per warp) ----
    float acc[2][8][4];
    #pragma unroll
    for (int mt = 0; mt < 2; mt++)
      #pragma unroll
      for (int nt = 0; nt < 8; nt++){
        acc[mt][nt][0]=0.f; acc[mt][nt][1]=0.f; acc[mt][nt][2]=0.f; acc[mt][nt][3]=0.f;
      }
    #pragma unroll
    for (int kt = 0; kt < 8; kt++){
      int ka = kt*8 + tig;
      unsigned aA0 = __float_as_uint(As[r0   ][ka]);
      unsigned aA1 = __float_as_uint(As[r0+ 8][ka]);
      unsigned aA2 = __float_as_uint(As[r0   ][ka+4]);
      unsigned aA3 = __float_as_uint(As[r0+ 8][ka+4]);
      unsigned aB0 = __float_as_uint(As[r0+16][ka]);
      unsigned aB1 = __float_as_uint(As[r0+24][ka]);
      unsigned aB2 = __float_as_uint(As[r0+16][ka+4]);
      unsigned aB3 = __float_as_uint(As[r0+24][ka+4]);
      #pragma unroll
      for (int nt = 0; nt < 8; nt++){
        unsigned b0v = __float_as_uint(W1[ka  ][nt*8+g]);
        unsigned b1v = __float_as_uint(W1[ka+4][nt*8+g]);
        mma_tf32(acc[0][nt], aA0, aA1, aA2, aA3, b0v, b1v);
        mma_tf32(acc[1][nt], aB0, aB1, aB2, aB3, b0v, b1v);
      }
    }

    // ---- epilogue1: h2 = tanh(acc + q[src] + b) -> As (own rows) ----
    #pragma unroll
    for (int mt = 0; mt < 2; mt++){
      int ra = r0 + mt*16, rb = ra + 8;
      int sa = s_src[ra], sb = s_src[rb];
      #pragma unroll
      for (int nt = 0; nt < 8; nt++){
        int c = nt*8 + 2*tig;
        float2 qa = *(const float2*)&gq[(size_t)sa*64 + c];
        float2 qb = *(const float2*)&gq[(size_t)sb*64 + c];
        float2 bv = *(const float2*)&bb[c];
        *(float2*)&As[ra][c] = make_float2(ftanh(acc[mt][nt][0]+qa.x+bv.x),
                                           ftanh(acc[mt][nt][1]+qa.y+bv.y));
        *(float2*)&As[rb][c] = make_float2(ftanh(acc[mt][nt][2]+qb.x+bv.x),
                                           ftanh(acc[mt][nt][3]+qb.y+bv.y));
      }
    }
    __syncwarp();

    // ---- GEMM2: h2 @ Wh ----
    #pragma unroll
    for (int mt = 0; mt < 2; mt++)
      #pragma unroll
      for (int nt = 0; nt < 8; nt++){
        acc[mt][nt][0]=0.f; acc[mt][nt][1]=0.f; acc[mt][nt][2]=0.f; acc[mt][nt][3]=0.f;
      }
    #pragma unroll
    for (int kt = 0; kt < 8; kt++){
      int ka = kt*8 + tig;
      unsigned aA0 = __float_as_uint(As[r0   ][ka]);
      unsigned aA1 = __float_as_uint(As[r0+ 8][ka]);
      unsigned aA2 = __float_as_uint(As[r0   ][ka+4]);
      unsigned aA3 = __float_as_uint(As[r0+ 8][ka+4]);
      unsigned aB0 = __float_as_uint(As[r0+16][ka]);
      unsigned aB1 = __float_as_uint(As[r0+24][ka]);
      unsigned aB2 = __float_as_uint(As[r0+16][ka+4]);
      unsigned aB3 = __float_as_uint(As[r0+24][ka+4]);
      #pragma unroll
      for (int nt = 0; nt < 8; nt++){
        unsigned b0v = __float_as_uint(W2[ka  ][nt*8+g]);
        unsigned b1v = __float_as_uint(W2[ka+4][nt*8+g]);
        mma_tf32(acc[0][nt], aA0, aA1, aA2, aA3, b0v, b1v);
        mma_tf32(acc[1][nt], aB0, aB1, aB2, aB3, b0v, b1v);
      }
    }

    // ---- epilogue2: h3 = tanh(acc + p[dst] + b); fp16 spill (enc0); attn dot ----
    #pragma unroll
    for (int mt = 0; mt < 2; mt++){
      int ra = r0 + mt*16, rb = ra + 8;
      int da = s_dst[ra], db = s_dst[rb];
      float ea0=0.f, ea1=0.f, eb0=0.f, eb1=0.f;
      #pragma unroll
      for (int nt = 0; nt < 8; nt++){
        int c = nt*8 + 2*tig;
        float2 pa = *(const float2*)&gp[(size_t)da*64 + c];
        float2 pb = *(const float2*)&gp[(size_t)db*64 + c];
        float2 bv = *(const float2*)&bb[c];
        float2 av = *(const float2*)&att[c];
        float hax = ftanh(acc[mt][nt][0]+pa.x+bv.x), hay = ftanh(acc[mt][nt][1]+pa.y+bv.y);
        float hbx = ftanh(acc[mt][nt][2]+pb.x+bv.x), hby = ftanh(acc[mt][nt][3]+pb.y+bv.y);
        if (enc == 0){
          *(__half2*)&g_h3[(size_t)(ebase+ra)*64 + c] = __floats2half2_rn(hax, hay);
          *(__half2*)&g_h3[(size_t)(ebase+rb)*64 + c] = __floats2half2_rn(hbx, hby);
        }
        float dva = hax*av.x + hay*av.y;
        float dvb = hbx*av.x + hby*av.y;
        if (nt < 4){ ea0 += dva; eb0 += dvb; }
        else       { ea1 += dva; eb1 += dvb; }
      }
      #pragma unroll
      for (int o = 1; o <= 2; o <<= 1){
        ea0 += __shfl_xor_sync(0xffffffffu, ea0, o);
        ea1 += __shfl_xor_sync(0xffffffffu, ea1, o);
        eb0 += __shfl_xor_sync(0xffffffffu, eb0, o);
        eb1 += __shfl_xor_sync(0xffffffffu, eb1, o);
      }
      edot[enc][mt*2  ][0] = ea0; edot[enc][mt*2  ][1] = ea1;
      edot[enc][mt*2+1][0] = eb0; edot[enc][mt*2+1][1] = eb1;
    }
  }

  if (tig == 0){
    #pragma unroll
    for (int head = 0; head < 2; head++){
      float se0 = fsigm(eta0[head]);
      float se1 = fsigm(eta1[head]);
      float gg  = fsigm(delta[head]);
      #pragma unroll
      for (int rs = 0; rs < 4; rs++){
        int e = ebase + r0 + rs*8;
        float sc = (1.0f - gg) * ftanh(se0 * edot[0][rs][head])
                 + gg          * ftanh(se1 * edot[1][rs][head]);
        g_s[e*2 + head] = sc;
      }
    }
  }
}

// warp-per-node aggregation (R12: single pass, fp16 h3, unnormalized weights)
__global__ void __launch_bounds__(256) k_agg(const int* __restrict__ src,
                                             const int* __restrict__ prob,
                                             float* __restrict__ out_mm,
                                             float* __restrict__ out_ms){
  int warp = (blockIdx.x * blockDim.x + threadIdx.x) >> 5;
  int lane = threadIdx.x & 31;
  if (warp >= NN) return;
  int node = warp;
  int cnt  = g_count[node];
  int base = g_off[node];

  int head = lane >> 4;
  float d0=0.f, d1=0.f, msum=0.f, mcnt=0.f, ssum=0.f, scnt=0.f;
  float fx=0.f, fy=0.f, f2x=0.f, f2y=0.f;

  for (int i0 = 0; i0 < cnt; i0 += 32){
    int ii = i0 + lane;
    float ex0 = 0.f, ex1 = 0.f;
    int ee = 0, sv = 0;
    if (ii < cnt){
      ee = g_perm[base + ii];
      float2 s = *(const float2*)&g_s[ee*2];
      ex0 = __expf(s.x);
      ex1 = __expf(s.y);
      d0 += ex0; d1 += ex1;
      float sc = 0.5f * (s.x + s.y);
      int p = prob[ee];
      if (p > 1){ msum += sc; mcnt += 1.f; }
      else if (p == 1){ ssum += sc; scnt += 1.f; }
      sv = src[ee];
    }
    int lim = min(32, cnt - i0);
    int j = 0;
    for (; j + 2 <= lim; j += 2){
      float ea0 = __shfl_sync(0xffffffffu, ex0, j);
      float ea1 = __shfl_sync(0xffffffffu, ex1, j);
      float eb0 = __shfl_sync(0xffffffffu, ex0, j+1);
      float eb1 = __shfl_sync(0xffffffffu, ex1, j+1);
      int eA  = __shfl_sync(0xffffffffu, ee, j);
      int eB  = __shfl_sync(0xffffffffu, ee, j+1);
      int sA  = __shfl_sync(0xffffffffu, sv, j);
      int sB  = __shfl_sync(0xffffffffu, sv, j+1);
      float aA = head ? ea1 : ea0;
      float aB = head ? eb1 : eb0;
      float2 huA = *(const float2*)&g_h[(size_t)sA*64 + 2*lane];
      float2 h3A = __half22float2(*(const __half2*)&g_h3[(size_t)eA*64 + 2*lane]);
      float2 huB = *(const float2*)&g_h[(size_t)sB*64 + 2*lane];
      float2 h3B = __half22float2(*(const __half2*)&g_h3[(size_t)eB*64 + 2*lane]);
      fx  += huA.x*aA + huB.x*aB;  fy  += huA.y*aA + huB.y*aB;
      f2x += h3A.x*aA + h3B.x*aB;  f2y += h3A.y*aA + h3B.y*aB;
    }
    if (j < lim){
      float ea0 = __shfl_sync(0xffffffffu, ex0, j);
      float ea1 = __shfl_sync(0xffffffffu, ex1, j);
      int eA  = __shfl_sync(0xffffffffu, ee, j);
      int sA  = __shfl_sync(0xffffffffu, sv, j);
      float aA = head ? ea1 : ea0;
      float2 huA = *(const float2*)&g_h[(size_t)sA*64 + 2*lane];
      float2 h3A = __half22float2(*(const __half2*)&g_h3[(size_t)eA*64 + 2*lane]);
      fx  += huA.x*aA;  fy  += huA.y*aA;
      f2x += h3A.x*aA;  f2y += h3A.y*aA;
    }
  }
  #pragma unroll
  for (int o = 16; o > 0; o >>= 1){
    d0   += __shfl_xor_sync(0xffffffffu, d0, o);
    d1   += __shfl_xor_sync(0xffffffffu, d1, o);
    msum += __shfl_xor_sync(0xffffffffu, msum, o);
    mcnt += __shfl_xor_sync(0xffffffffu, mcnt, o);
    ssum += __shfl_xor_sync(0xffffffffu, ssum, o);
    scnt += __shfl_xor_sync(0xffffffffu, scnt, o);
  }
  float inv0 = __fdividef(1.f, fmaxf(d0, 1e-9f));
  float inv1 = __fdividef(1.f, fmaxf(d1, 1e-9f));
  float invh = head ? inv1 : inv0;

  *(float2*)&g_ft [(size_t)node*64 + 2*lane] = make_float2(fx*invh, fy*invh);
  *(float2*)&g_ft2[(size_t)node*64 + 2*lane] = make_float2(f2x*invh, f2y*invh);

  if (lane == 0){
    float ind = (mcnt > 0.f && scnt > 0.f) ? 1.f : 0.f;
    float mm = msum / (mcnt > 0.f ? mcnt : 1.f);
    float ms = ssum / (scnt > 0.f ? scnt : 1.f);
    out_mm[node] = mm * ind;
    out_ms[node] = ms * ind;
  }
}

__global__ void __launch_bounds__(256) k_out(const float* __restrict__ Wsrc, const float* __restrict__ bsrc,
                                             const float* __restrict__ Wedge, const float* __restrict__ bedge,
                                             float* __restrict__ out){
  __shared__ float fts [64][68];
  __shared__ float ft2s[64][68];
  __shared__ float Ws[32][36];
  __shared__ float We[32][36];
  int t = threadIdx.x;
  int r0 = blockIdx.x * 64;
  #pragma unroll
  for (int j = 0; j < 4; j++){
    int idx = t + 256*j;
    int r = idx >> 4, c4 = (idx & 15) * 4;
    float4 v1 = make_float4(0.f,0.f,0.f,0.f), v2 = v1;
    if (r0 + r < NN){
      v1 = *(const float4*)&g_ft [(size_t)(r0+r)*64 + c4];
      v2 = *(const float4*)&g_ft2[(size_t)(r0+r)*64 + c4];
    }
    *(float4*)&fts [r][c4] = v1;
    *(float4*)&ft2s[r][c4] = v2;
  }
  {
    int r = t >> 3, c4 = (t & 7) * 4;
    *(float4*)&Ws[r][c4] = *(const float4*)&Wsrc [r*32 + c4];
    *(float4*)&We[r][c4] = *(const float4*)&Wedge[r*32 + c4];
  }
  __syncthreads();

  int cg = t & 7, eg = t >> 3;
  int c0 = cg * 8, rr = eg * 2;
  int hd = c0 >> 5, dl = c0 & 31;
  float acc[2][8] = {};
  #pragma unroll
  for (int k = 0; k < 32; k++){
    float a0 = fts [rr  ][hd*32 + k], a1 = fts [rr+1][hd*32 + k];
    float c0v= ft2s[rr  ][hd*32 + k], c1v= ft2s[rr+1][hd*32 + k];
    float4 w0 = *(const float4*)&Ws[k][dl];
    float4 w1 = *(const float4*)&Ws[k][dl+4];
    ROW_FMA8(acc[0], a0);
    ROW_FMA8(acc[1], a1);
    w0 = *(const float4*)&We[k][dl];
    w1 = *(const float4*)&We[k][dl+4];
    ROW_FMA8(acc[0], c0v);
    ROW_FMA8(acc[1], c1v);
  }
  float bs[8], be[8];
  *(float4*)&bs[0] = *(const float4*)&bsrc [dl];
  *(float4*)&bs[4] = *(const float4*)&bsrc [dl+4];
  *(float4*)&be[0] = *(const float4*)&bedge[dl];
  *(float4*)&be[4] = *(const float4*)&bedge[dl+4];
  #pragma unroll
  for (int i = 0; i < 2; i++){
    int r = r0 + rr + i;
    if (r < NN){
      float4 h0 = *(const float4*)&g_h[(size_t)r*64 + c0];
      float4 h1 = *(const float4*)&g_h[(size_t)r*64 + c0+4];
      float o[8];
      o[0]=acc[i][0]+bs[0]+be[0]+h0.x; o[1]=acc[i][1]+bs[1]+be[1]+h0.y;
      o[2]=acc[i][2]+bs[2]+be[2]+h0.z; o[3]=acc[i][3]+bs[3]+be[3]+h0.w;
      o[4]=acc[i][4]+bs[4]+be[4]+h1.x; o[5]=acc[i][5]+bs[5]+be[5]+h1.y;
      o[6]=acc[i][6]+bs[6]+be[6]+h1.z; o[7]=acc[i][7]+bs[7]+be[7]+h1.w;
      #pragma unroll
      for (int j = 0; j < 8; j++) o[j] = fmaxf(o[j], 0.f);
      *(float4*)&out[(size_t)r*64 + c0]   = *(float4*)&o[0];
      *(float4*)&out[(size_t)r*64 + c0+4] = *(float4*)&o[4];
    }
  }
}

extern "C" void kernel_launch(void* const* d_in, const int* in_sizes, int n_in,
                              void* d_out, int out_size){
  const float* x     = (const float*)d_in[0];
  const float* ef0   = (const float*)d_in[1];
  const float* ef1   = (const float*)d_in[2];
  const int*   src   = (const int*)  d_in[3];
  const int*   dst   = (const int*)  d_in[4];
  const int*   prob  = (const int*)  d_in[5];
  const float* W_lin = (const float*)d_in[6];
  const float* b_lin = (const float*)d_in[7];
  const float* Wx0   = (const float*)d_in[8];
  const float* Wh0   = (const float*)d_in[9];
  const float* b0    = (const float*)d_in[10];
  const float* Wx1   = (const float*)d_in[11];
  const float* Wh1   = (const float*)d_in[12];
  const float* b1    = (const float*)d_in[13];
  const float* attn0 = (const float*)d_in[14];
  const float* eta0  = (const float*)d_in[15];
  const float* attn1 = (const float*)d_in[16];
  const float* eta1  = (const float*)d_in[17];
  const float* delta = (const float*)d_in[18];
  const float* Wsrc  = (const float*)d_in[19];
  const float* bsrc  = (const float*)d_in[20];
  const float* Wedge = (const float*)d_in[21];
  const float* bedge = (const float*)d_in[22];

  float* out    = (float*)d_out;
  float* out_mm = out + (size_t)NN*64;
  float* out_ms = out_mm + NN;

  const int EDGE_SMEM = 384*72*(int)sizeof(float) + 512*(int)sizeof(int);
  const int NODE_SMEM = 3 * 64 * 68 * (int)sizeof(float);
  cudaFuncSetAttribute(k_edge1, cudaFuncAttributeMaxDynamicSharedMemorySize, EDGE_SMEM);
  cudaFuncSetAttribute(k_node,  cudaFuncAttributeMaxDynamicSharedMemorySize, NODE_SMEM);

  // Fork a side branch in the captured graph for the CSR build.
  cudaStream_t side;
  cudaEvent_t ev_fork, ev_join;
  cudaStreamCreateWithFlags(&side, cudaStreamNonBlocking);
  cudaEventCreateWithFlags(&ev_fork, cudaEventDisableTiming);
  cudaEventCreateWithFlags(&ev_join, cudaEventDisableTiming);

  cudaEventRecord(ev_fork, 0);
  cudaStreamWaitEvent(side, ev_fork, 0);
  k_zero<<<(NN+255)/256, 256, 0, side>>>();
  k_hist<<<(NE+255)/256, 256, 0, side>>>(dst);
  k_scan<<<1, 1024, 0, side>>>();
  k_scatter<<<(NE+255)/256, 256, 0, side>>>(dst);
  cudaEventRecord(ev_join, side);

  // Main branch
  k_node<<<(NN+63)/64, 256, NODE_SMEM>>>(x, W_lin, b_lin,
      Wx0, Wh0, b0, Wx1, Wh1, b1);
  k_edge1<<<NE/256, 256, EDGE_SMEM>>>(ef0, ef1, src, dst,
      Wx0, Wh0, b0, Wx1, Wh1, b1, attn0, eta0, attn1, eta1, delta);

  cudaStreamWaitEvent(0, ev_join, 0);
  k_agg<<<(NN*32+255)/256, 256>>>(src, prob, out_mm, out_ms);
  k_out<<<(NN+63)/64, 256>>>(Wsrc, bsrc, Wedge, bedge, out);
  // Stream/events intentionally not destroyed (capture safety); replays
  // do not re-enter kernel_launch.
}

// round 16
// speedup vs baseline: 1.0058x; 1.0058x over previous
#include <cuda_runtime.h>
#include <cuda_fp16.h>
#include <math.h>

#define NN 50000
#define NE 800000

__device__ float  g_h [NN*64];
__device__ __half g_hh[NN*64];          // fp16 shadow of h for k_agg gathers
__device__ __half g_p0[NN*64];
__device__ __half g_q0[NN*64];
__device__ __half g_p1[NN*64];
__device__ __half g_q1[NN*64];
__device__ float  g_ft [NN*64];
__device__ float  g_ft2[NN*64];
__device__ __half g_h3[(size_t)NE*64];
__device__ float  g_s [NE*2];
__device__ int    g_count [NN];
__device__ int    g_off   [NN];
__device__ int    g_cursor[NN];
__device__ int    g_perm  [NE];

__device__ __forceinline__ float ftanh(float x){
    float e = __expf(2.0f*x);
    return 1.0f - __fdividef(2.0f, e + 1.0f);
}
__device__ __forceinline__ float fsigm(float x){
    return __fdividef(1.0f, 1.0f + __expf(-x));
}

#define KK_COMP(v,kk) ((kk)==0?(v).x:((kk)==1?(v).y:((kk)==2?(v).z:(v).w)))
#define ROW_FMA8(ar, va) do{ \
  ar[0] += (va)*w0.x; ar[1] += (va)*w0.y; ar[2] += (va)*w0.z; ar[3] += (va)*w0.w; \
  ar[4] += (va)*w1.x; ar[5] += (va)*w1.y; ar[6] += (va)*w1.z; ar[7] += (va)*w1.w; }while(0)

__device__ __forceinline__ void gemm2x8(const float (*A)[68], const float (*W)[68],
                                        int rr, int c0, float acc[2][8]){
  #pragma unroll
  for (int k = 0; k < 64; k += 4){
    float4 a0 = *(const float4*)&A[rr+0][k];
    float4 a1 = *(const float4*)&A[rr+1][k];
    #pragma unroll
    for (int kk = 0; kk < 4; kk++){
      float4 w0 = *(const float4*)&W[k+kk][c0];
      float4 w1 = *(const float4*)&W[k+kk][c0+4];
      float va0 = KK_COMP(a0,kk), va1 = KK_COMP(a1,kk);
      ROW_FMA8(acc[0], va0); ROW_FMA8(acc[1], va1);
    }
  }
}

// tf32 m16n8k8 mma, fp32 accumulate
__device__ __forceinline__ void mma_tf32(float c[4], unsigned a0, unsigned a1,
                                         unsigned a2, unsigned a3,
                                         unsigned b0, unsigned b1){
  asm("mma.sync.aligned.m16n8k8.row.col.f32.tf32.tf32.f32 "
      "{%0,%1,%2,%3}, {%4,%5,%6,%7}, {%8,%9}, {%0,%1,%2,%3};"
      : "+f"(c[0]), "+f"(c[1]), "+f"(c[2]), "+f"(c[3])
      : "r"(a0), "r"(a1), "r"(a2), "r"(a3), "r"(b0), "r"(b1));
}

__global__ void k_zero(){
  int i = blockIdx.x*256 + threadIdx.x;
  if (i < NN) g_count[i] = 0;
}
__global__ void k_hist(const int* __restrict__ dst){
  int e = blockIdx.x*256 + threadIdx.x;
  if (e < NE) atomicAdd(&g_count[dst[e]], 1);
}
__global__ void __launch_bounds__(1024) k_scan(){
  __shared__ int wsum[32];
  __shared__ int carry_s;
  int t = threadIdx.x, lane = t & 31, wid = t >> 5;
  if (t == 0) carry_s = 0;
  __syncthreads();
  for (int c = 0; c < NN; c += 1024){
    int i = c + t;
    int v = (i < NN) ? g_count[i] : 0;
    int s = v;
    #pragma unroll
    for (int o = 1; o < 32; o <<= 1){
      int n = __shfl_up_sync(0xffffffffu, s, o);
      if (lane >= o) s += n;
    }
    if (lane == 31) wsum[wid] = s;
    __syncthreads();
    if (wid == 0){
      int ws = wsum[lane];
      #pragma unroll
      for (int o = 1; o < 32; o <<= 1){
        int n = __shfl_up_sync(0xffffffffu, ws, o);
        if (lane >= o) ws += n;
      }
      wsum[lane] = ws;
    }
    __syncthreads();
    int carry = carry_s;
    int excl = s - v + (wid ? wsum[wid-1] : 0) + carry;
    if (i < NN){ g_off[i] = excl; g_cursor[i] = excl; }
    int total = wsum[31];
    __syncthreads();
    if (t == 0) carry_s = carry + total;
    __syncthreads();
  }
}
__global__ void k_scatter(const int* __restrict__ dst){
  int e = blockIdx.x*256 + threadIdx.x;
  if (e < NE){
    int d = dst[e];
    int pos = atomicAdd(&g_cursor[d], 1);
    g_perm[pos] = e;
  }
}

// Fused node kernel; p/q written fp16, h written fp32 + fp16 shadow.
__global__ void __launch_bounds__(256) k_node(
    const float* __restrict__ x, const float* __restrict__ W_lin, const float* __restrict__ b_lin,
    const float* __restrict__ Wx0, const float* __restrict__ Wh0, const float* __restrict__ b0,
    const float* __restrict__ Wx1, const float* __restrict__ Wh1, const float* __restrict__ b1){
  extern __shared__ float sm[];
  float (*Xs)[68] = (float(*)[68])sm;
  float (*Ws)[68] = (float(*)[68])(sm + 64*68);
  float (*Ts)[68] = (float(*)[68])(sm + 2*64*68);
  int t = threadIdx.x;
  int r0 = blockIdx.x * 64;
  #pragma unroll
  for (int j = 0; j < 4; j++){
    int idx = t + 256*j;
    int r = idx >> 4, c4 = (idx & 15) * 4;
    float4 v = make_float4(0.f,0.f,0.f,0.f);
    if (r0 + r < NN) v = *(const float4*)&x[(size_t)(r0+r)*64 + c4];
    *(float4*)&Xs[r][c4] = v;
    *(float4*)&Ws[r][c4] = *(const float4*)&W_lin[r*64 + c4];
  }
  __syncthreads();
  int cg = t & 7, eg = t >> 3;
  int c0 = cg * 8, rr = eg * 2;

  float hacc[2][8] = {};
  gemm2x8(Xs, Ws, rr, c0, hacc);
  float bv[8];
  *(float4*)&bv[0] = *(const float4*)&b_lin[c0];
  *(float4*)&bv[4] = *(const float4*)&b_lin[c0+4];
  float hval[2][8];
  #pragma unroll
  for (int i = 0; i < 2; i++){
    #pragma unroll
    for (int j = 0; j < 8; j++) hval[i][j] = hacc[i][j] + bv[j];
    int r = r0 + rr + i;
    if (r < NN){
      *(float4*)&g_h[(size_t)r*64 + c0]   = *(float4*)&hval[i][0];
      *(float4*)&g_h[(size_t)r*64 + c0+4] = *(float4*)&hval[i][4];
      #pragma unroll
      for (int j = 0; j < 4; j++)
        *(__half2*)&g_hh[(size_t)r*64 + c0 + 2*j] = __floats2half2_rn(hval[i][2*j], hval[i][2*j+1]);
    }
  }
  __syncthreads();
  #pragma unroll
  for (int i = 0; i < 2; i++){
    *(float4*)&Xs[rr+i][c0]   = *(float4*)&hval[i][0];
    *(float4*)&Xs[rr+i][c0+4] = *(float4*)&hval[i][4];
  }

  for (int enc = 0; enc < 2; enc++){
    const float* Wx = enc ? Wx1 : Wx0;
    const float* Wh = enc ? Wh1 : Wh0;
    const float* bb = enc ? b1  : b0;
    __half* gp = enc ? g_p1 : g_p0;
    __half* gq = enc ? g_q1 : g_q0;
    __syncthreads();
    #pragma unroll
    for (int j = 0; j < 4; j++){
      int idx = t + 256*j;
      int r = idx >> 4, c4 = (idx & 15) * 4;
      *(float4*)&Ws[r][c4] = *(const float4*)&Wx[r*64 + c4];
    }
    __syncthreads();
    float acc[2][8] = {};
    gemm2x8(Xs, Ws, rr, c0, acc);
    *(float4*)&bv[0] = *(const float4*)&bb[c0];
    *(float4*)&bv[4] = *(const float4*)&bb[c0+4];
    #pragma unroll
    for (int i = 0; i < 2; i++){
      int r = r0 + rr + i;
      if (r < NN){
        #pragma unroll
        for (int j = 0; j < 4; j++)
          *(__half2*)&gp[(size_t)r*64 + c0 + 2*j] = __floats2half2_rn(acc[i][2*j], acc[i][2*j+1]);
      }
      #pragma unroll
      for (int j = 0; j < 8; j++) Ts[rr+i][c0+j] = ftanh(acc[i][j] + bv[j]);
    }
    __syncthreads();
    #pragma unroll
    for (int j = 0; j < 4; j++){
      int idx = t + 256*j;
      int r = idx >> 4, c4 = (idx & 15) * 4;
      *(float4*)&Ws[r][c4] = *(const float4*)&Wh[r*64 + c4];
    }
    __syncthreads();
    float acc2[2][8] = {};
    gemm2x8(Ts, Ws, rr, c0, acc2);
    #pragma unroll
    for (int i = 0; i < 2; i++){
      int r = r0 + rr + i;
      if (r < NN){
        #pragma unroll
        for (int j = 0; j < 4; j++)
          *(__half2*)&gq[(size_t)r*64 + c0 + 2*j] = __floats2half2_rn(acc2[i][2*j], acc2[i][2*j+1]);
      }
    }
  }
}

// Edge pass (R12 config): 128 edges/block, fp16 q/p gathers prefetched behind MMAs.
__global__ void __launch_bounds__(256) k_edge1(
    const float* __restrict__ ef0, const float* __restrict__ ef1,
    const int* __restrict__ src, const int* __restrict__ dst,
    const float* __restrict__ Wx0, const float* __restrict__ Wh0, const float* __restrict__ b0,
    const float* __restrict__ Wx1, const float* __restrict__ Wh1, const float* __restrict__ b1,
    const float* __restrict__ attn0, const float* __restrict__ eta0,
    const float* __restrict__ attn1, const float* __restrict__ eta1,
    const float* __restrict__ delta)
{
  extern __shared__ float sm[];
  float (*As)[72] = (float(*)[72])sm;              // 128 x 72
  float (*W1)[72] = (float(*)[72])(sm + 128*72);   // Wx 64 x 72
  float (*W2)[72] = (float(*)[72])(sm + 192*72);   // Wh 64 x 72
  int* s_src = (int*)(sm + 256*72);
  int* s_dst = s_src + 128;

  int t = threadIdx.x;
  int ebase = blockIdx.x * 128;
  if (t < 128) s_src[t] = src[ebase + t];
  else         s_dst[t-128] = dst[ebase + t - 128];

  int w = t >> 5, lane = t & 31;
  int g = lane >> 2, tig = lane & 3;
  int row0 = w*16 + g, row1 = row0 + 8;

  float edot[2][2][2];

  for (int enc = 0; enc < 2; enc++){
    const float* ef  = enc ? ef1  : ef0;
    const float* Wx  = enc ? Wx1  : Wx0;
    const float* Wh  = enc ? Wh1  : Wh0;
    const float* bb  = enc ? b1   : b0;
    const __half* gq = enc ? g_q1 : g_q0;
    const __half* gp = enc ? g_p1 : g_p0;
    const float* att = enc ? attn1 : attn0;

    __syncthreads();
    #pragma unroll
    for (int j = 0; j < 8; j++){
      int idx = t + 256*j;
      int e = idx >> 4, c4 = (idx & 15) * 4;
      *(float4*)&As[e][c4] = *(const float4*)&ef[(size_t)(ebase+e)*64 + c4];
    }
    #pragma unroll
    for (int j = 0; j < 4; j++){
      int idx = t + 256*j;
      int r = idx >> 4, c4 = (idx & 15) * 4;
      *(float4*)&W1[r][c4] = *(const float4*)&Wx[r*64 + c4];
      *(float4*)&W2[r][c4] = *(const float4*)&Wh[r*64 + c4];
    }
    __syncthreads();

    int s0 = s_src[row0], s1 = s_src[row1];
    int d0 = s_dst[row0], d1 = s_dst[row1];

    // ---- prefetch q[src] (fp16, hidden behind GEMM1) ----
    float2 pf0[8], pf1[8];
    #pragma unroll
    for (int nt = 0; nt < 8; nt++){
      int c = nt*8 + 2*tig;
      pf0[nt] = __half22float2(*(const __half2*)&gq[(size_t)s0*64 + c]);
      pf1[nt] = __half22float2(*(const __half2*)&gq[(size_t)s1*64 + c]);
    }

    // ---- GEMM1: ef @ Wx ----
    float acc[8][4];
    #pragma unroll
    for (int nt = 0; nt < 8; nt++){ acc[nt][0]=0.f; acc[nt][1]=0.f; acc[nt][2]=0.f; acc[nt][3]=0.f; }
    #pragma unroll
    for (int kt = 0; kt < 8; kt++){
      int ka = kt*8 + tig;
      unsigned a0 = __float_as_uint(As[row0][ka]);
      unsigned a1 = __float_as_uint(As[row1][ka]);
      unsigned a2 = __float_as_uint(As[row0][ka+4]);
      unsigned a3 = __float_as_uint(As[row1][ka+4]);
      #pragma unroll
      for (int nt = 0; nt < 8; nt++){
        unsigned b0v = __float_as_uint(W1[ka  ][nt*8+g]);
        unsigned b1v = __float_as_uint(W1[ka+4][nt*8+g]);
        mma_tf32(acc[nt], a0, a1, a2, a3, b0v, b1v);
      }
    }

    // ---- epilogue1 ----
    #pragma unroll
    for (int nt = 0; nt < 8; nt++){
      int c = nt*8 + 2*tig;
      float2 bv = *(const float2*)&bb[c];
      *(float2*)&As[row0][c] = make_float2(ftanh(acc[nt][0]+pf0[nt].x+bv.x),
                                           ftanh(acc[nt][1]+pf0[nt].y+bv.y));
      *(float2*)&As[row1][c] = make_float2(ftanh(acc[nt][2]+pf1[nt].x+bv.x),
                                           ftanh(acc[nt][3]+pf1[nt].y+bv.y));
    }
    __syncwarp();

    // ---- prefetch p[dst] (fp16, hidden behind GEMM2) ----
    #pragma unroll
    for (int nt = 0; nt < 8; nt++){
      int c = nt*8 + 2*tig;
      pf0[nt] = __half22float2(*(const __half2*)&gp[(size_t)d0*64 + c]);
      pf1[nt] = __half22float2(*(const __half2*)&gp[(size_t)d1*64 + c]);
    }

    // ---- GEMM2: h2 @ Wh ----
    #pragma unroll
    for (int nt = 0; nt < 8; nt++){ acc[nt][0]=0.f; acc[nt][1]=0.f; acc[nt][2]=0.f; acc[nt][3]=0.f; }
    #pragma unroll
    for (int kt = 0; kt < 8; kt++){
      int ka = kt*8 + tig;
      unsigned a0 = __float_as_uint(As[row0][ka]);
      unsigned a1 = __float_as_uint(As[row1][ka]);
      unsigned a2 = __float_as_uint(As[row0][ka+4]);
      unsigned a3 = __float_as_uint(As[row1][ka+4]);
      #pragma unroll
      for (int nt = 0; nt < 8; nt++){
        unsigned b0v = __float_as_uint(W2[ka  ][nt*8+g]);
        unsigned b1v = __float_as_uint(W2[ka+4][nt*8+g]);
        mma_tf32(acc[nt], a0, a1, a2, a3, b0v, b1v);
      }
    }

    // ---- epilogue2 ----
    float dt00=0.f, dt01=0.f, dt10=0.f, dt11=0.f;
    #pragma unroll
    for (int nt = 0; nt < 8; nt++){
      int c = nt*8 + 2*tig;
      float2 bv = *(const float2*)&bb[c];
      float2 av = *(const float2*)&att[c];
      float h0x = ftanh(acc[nt][0]+pf0[nt].x+bv.x), h0y = ftanh(acc[nt][1]+pf0[nt].y+bv.y);
      float h1x = ftanh(acc[nt][2]+pf1[nt].x+bv.x), h1y = ftanh(acc[nt][3]+pf1[nt].y+bv.y);
      if (enc == 0){
        *(__half2*)&g_h3[(size_t)(ebase+row0)*64 + c] = __floats2half2_rn(h0x, h0y);
        *(__half2*)&g_h3[(size_t)(ebase+row1)*64 + c] = __floats2half2_rn(h1x, h1y);
      }
      float d0v = h0x*av.x + h0y*av.y;
      float d1v = h1x*av.x + h1y*av.y;
      if (nt < 4){ dt00 += d0v; dt10 += d1v; }
      else       { dt01 += d0v; dt11 += d1v; }
    }
    #pragma unroll
    for (int o = 1; o <= 2; o <<= 1){
      dt00 += __shfl_xor_sync(0xffffffffu, dt00, o);
      dt01 += __shfl_xor_sync(0xffffffffu, dt01, o);
      dt10 += __shfl_xor_sync(0xffffffffu, dt10, o);
      dt11 += __shfl_xor_sync(0xffffffffu, dt11, o);
    }
    edot[enc][0][0] = dt00; edot[enc][0][1] = dt01;
    edot[enc][1][0] = dt10; edot[enc][1][1] = dt11;
  }

  if (tig == 0){
    #pragma unroll
    for (int head = 0; head < 2; head++){
      float se0 = fsigm(eta0[head]);
      float se1 = fsigm(eta1[head]);
      float gg  = fsigm(delta[head]);
      #pragma unroll
      for (int rh = 0; rh < 2; rh++){
        int e = ebase + row0 + rh*8;
        float sc = (1.0f - gg) * ftanh(se0 * edot[0][rh][head])
                 + gg          * ftanh(se1 * edot[1][rh][head]);
        g_s[e*2 + head] = sc;
      }
    }
  }
}

// warp-per-node aggregation: single pass, fp16 gathers for hu and h3.
__global__ void __launch_bounds__(256) k_agg(const int* __restrict__ src,
                                             const int* __restrict__ prob,
                                             float* __restrict__ out_mm,
                                             float* __restrict__ out_ms){
  int warp = (blockIdx.x * blockDim.x + threadIdx.x) >> 5;
  int lane = threadIdx.x & 31;
  if (warp >= NN) return;
  int node = warp;
  int cnt  = g_count[node];
  int base = g_off[node];

  int head = lane >> 4;
  float d0=0.f, d1=0.f, msum=0.f, mcnt=0.f, ssum=0.f, scnt=0.f;
  float fx=0.f, fy=0.f, f2x=0.f, f2y=0.f;

  for (int i0 = 0; i0 < cnt; i0 += 32){
    int ii = i0 + lane;
    float ex0 = 0.f, ex1 = 0.f;
    int ee = 0, sv = 0;
    if (ii < cnt){
      ee = g_perm[base + ii];
      float2 s = *(const float2*)&g_s[ee*2];
      ex0 = __expf(s.x);
      ex1 = __expf(s.y);
      d0 += ex0; d1 += ex1;
      float sc = 0.5f * (s.x + s.y);
      int p = prob[ee];
      if (p > 1){ msum += sc; mcnt += 1.f; }
      else if (p == 1){ ssum += sc; scnt += 1.f; }
      sv = src[ee];
    }
    int lim = min(32, cnt - i0);
    int j = 0;
    for (; j + 2 <= lim; j += 2){
      float ea0 = __shfl_sync(0xffffffffu, ex0, j);
      float ea1 = __shfl_sync(0xffffffffu, ex1, j);
      float eb0 = __shfl_sync(0xffffffffu, ex0, j+1);
      float eb1 = __shfl_sync(0xffffffffu, ex1, j+1);
      int eA  = __shfl_sync(0xffffffffu, ee, j);
      int eB  = __shfl_sync(0xffffffffu, ee, j+1);
      int sA  = __shfl_sync(0xffffffffu, sv, j);
      int sB  = __shfl_sync(0xffffffffu, sv, j+1);
      float aA = head ? ea1 : ea0;
      float aB = head ? eb1 : eb0;
      float2 huA = __half22float2(*(const __half2*)&g_hh[(size_t)sA*64 + 2*lane]);
      float2 h3A = __half22float2(*(const __half2*)&g_h3[(size_t)eA*64 + 2*lane]);
      float2 huB = __half22float2(*(const __half2*)&g_hh[(size_t)sB*64 + 2*lane]);
      float2 h3B = __half22float2(*(const __half2*)&g_h3[(size_t)eB*64 + 2*lane]);
      fx  += huA.x*aA + huB.x*aB;  fy  += huA.y*aA + huB.y*aB;
      f2x += h3A.x*aA + h3B.x*aB;  f2y += h3A.y*aA + h3B.y*aB;
    }
    if (j < lim){
      float ea0 = __shfl_sync(0xffffffffu, ex0, j);
      float ea1 = __shfl_sync(0xffffffffu, ex1, j);
      int eA  = __shfl_sync(0xffffffffu, ee, j);
      int sA  = __shfl_sync(0xffffffffu, sv, j);
      float aA = head ? ea1 : ea0;
      float2 huA = __half22float2(*(const __half2*)&g_hh[(size_t)sA*64 + 2*lane]);
      float2 h3A = __half22float2(*(const __half2*)&g_h3[(size_t)eA*64 + 2*lane]);
      fx  += huA.x*aA;  fy  += huA.y*aA;
      f2x += h3A.x*aA;  f2y += h3A.y*aA;
    }
  }
  #pragma unroll
  for (int o = 16; o > 0; o >>= 1){
    d0   += __shfl_xor_sync(0xffffffffu, d0, o);
    d1   += __shfl_xor_sync(0xffffffffu, d1, o);
    msum += __shfl_xor_sync(0xffffffffu, msum, o);
    mcnt += __shfl_xor_sync(0xffffffffu, mcnt, o);
    ssum += __shfl_xor_sync(0xffffffffu, ssum, o);
    scnt += __shfl_xor_sync(0xffffffffu, scnt, o);
  }
  float inv0 = __fdividef(1.f, fmaxf(d0, 1e-9f));
  float inv1 = __fdividef(1.f, fmaxf(d1, 1e-9f));
  float invh = head ? inv1 : inv0;

  *(float2*)&g_ft [(size_t)node*64 + 2*lane] = make_float2(fx*invh, fy*invh);
  *(float2*)&g_ft2[(size_t)node*64 + 2*lane] = make_float2(f2x*invh, f2y*invh);

  if (lane == 0){
    float ind = (mcnt > 0.f && scnt > 0.f) ? 1.f : 0.f;
    float mm = msum / (mcnt > 0.f ? mcnt : 1.f);
    float ms = ssum / (scnt > 0.f ? scnt : 1.f);
    out_mm[node] = mm * ind;
    out_ms[node] = ms * ind;
  }
}

__global__ void __launch_bounds__(256) k_out(const float* __restrict__ Wsrc, const float* __restrict__ bsrc,
                                             const float* __restrict__ Wedge, const float* __restrict__ bedge,
                                             float* __restrict__ out){
  __shared__ float fts [64][68];
  __shared__ float ft2s[64][68];
  __shared__ float Ws[32][36];
  __shared__ float We[32][36];
  int t = threadIdx.x;
  int r0 = blockIdx.x * 64;
  #pragma unroll
  for (int j = 0; j < 4; j++){
    int idx = t + 256*j;
    int r = idx >> 4, c4 = (idx & 15) * 4;
    float4 v1 = make_float4(0.f,0.f,0.f,0.f), v2 = v1;
    if (r0 + r < NN){
      v1 = *(const float4*)&g_ft [(size_t)(r0+r)*64 + c4];
      v2 = *(const float4*)&g_ft2[(size_t)(r0+r)*64 + c4];
    }
    *(float4*)&fts [r][c4] = v1;
    *(float4*)&ft2s[r][c4] = v2;
  }
  {
    int r = t >> 3, c4 = (t & 7) * 4;
    *(float4*)&Ws[r][c4] = *(const float4*)&Wsrc [r*32 + c4];
    *(float4*)&We[r][c4] = *(const float4*)&Wedge[r*32 + c4];
  }
  __syncthreads();

  int cg = t & 7, eg = t >> 3;
  int c0 = cg * 8, rr = eg * 2;
  int hd = c0 >> 5, dl = c0 & 31;
  float acc[2][8] = {};
  #pragma unroll
  for (int k = 0; k < 32; k++){
    float a0 = fts [rr  ][hd*32 + k], a1 = fts [rr+1][hd*32 + k];
    float c0v= ft2s[rr  ][hd*32 + k], c1v= ft2s[rr+1][hd*32 + k];
    float4 w0 = *(const float4*)&Ws[k][dl];
    float4 w1 = *(const float4*)&Ws[k][dl+4];
    ROW_FMA8(acc[0], a0);
    ROW_FMA8(acc[1], a1);
    w0 = *(const float4*)&We[k][dl];
    w1 = *(const float4*)&We[k][dl+4];
    ROW_FMA8(acc[0], c0v);
    ROW_FMA8(acc[1], c1v);
  }
  float bs[8], be[8];
  *(float4*)&bs[0] = *(const float4*)&bsrc [dl];
  *(float4*)&bs[4] = *(const float4*)&bsrc [dl+4];
  *(float4*)&be[0] = *(const float4*)&bedge[dl];
  *(float4*)&be[4] = *(const float4*)&bedge[dl+4];
  #pragma unroll
  for (int i = 0; i < 2; i++){
    int r = r0 + rr + i;
    if (r < NN){
      float4 h0 = *(const float4*)&g_h[(size_t)r*64 + c0];
      float4 h1 = *(const float4*)&g_h[(size_t)r*64 + c0+4];
      float o[8];
      o[0]=acc[i][0]+bs[0]+be[0]+h0.x; o[1]=acc[i][1]+bs[1]+be[1]+h0.y;
      o[2]=acc[i][2]+bs[2]+be[2]+h0.z; o[3]=acc[i][3]+bs[3]+be[3]+h0.w;
      o[4]=acc[i][4]+bs[4]+be[4]+h1.x; o[5]=acc[i][5]+bs[5]+be[5]+h1.y;
      o[6]=acc[i][6]+bs[6]+be[6]+h1.z; o[7]=acc[i][7]+bs[7]+be[7]+h1.w;
      #pragma unroll
      for (int j = 0; j < 8; j++) o[j] = fmaxf(o[j], 0.f);
      *(float4*)&out[(size_t)r*64 + c0]   = *(float4*)&o[0];
      *(float4*)&out[(size_t)r*64 + c0+4] = *(float4*)&o[4];
    }
  }
}

extern "C" void kernel_launch(void* const* d_in, const int* in_sizes, int n_in,
                              void* d_out, int out_size){
  const float* x     = (const float*)d_in[0];
  const float* ef0   = (const float*)d_in[1];
  const float* ef1   = (const float*)d_in[2];
  const int*   src   = (const int*)  d_in[3];
  const int*   dst   = (const int*)  d_in[4];
  const int*   prob  = (const int*)  d_in[5];
  const float* W_lin = (const float*)d_in[6];
  const float* b_lin = (const float*)d_in[7];
  const float* Wx0   = (const float*)d_in[8];
  const float* Wh0   = (const float*)d_in[9];
  const float* b0    = (const float*)d_in[10];
  const float* Wx1   = (const float*)d_in[11];
  const float* Wh1   = (const float*)d_in[12];
  const float* b1    = (const float*)d_in[13];
  const float* attn0 = (const float*)d_in[14];
  const float* eta0  = (const float*)d_in[15];
  const float* attn1 = (const float*)d_in[16];
  const float* eta1  = (const float*)d_in[17];
  const float* delta = (const float*)d_in[18];
  const float* Wsrc  = (const float*)d_in[19];
  const float* bsrc  = (const float*)d_in[20];
  const float* Wedge = (const float*)d_in[21];
  const float* bedge = (const float*)d_in[22];

  float* out    = (float*)d_out;
  float* out_mm = out + (size_t)NN*64;
  float* out_ms = out_mm + NN;

  const int EDGE_SMEM = 256*72*(int)sizeof(float) + 256*(int)sizeof(int);
  const int NODE_SMEM = 3 * 64 * 68 * (int)sizeof(float);
  cudaFuncSetAttribute(k_edge1, cudaFuncAttributeMaxDynamicSharedMemorySize, EDGE_SMEM);
  cudaFuncSetAttribute(k_node,  cudaFuncAttributeMaxDynamicSharedMemorySize, NODE_SMEM);

  // Fork a side branch in the captured graph for the CSR build.
  cudaStream_t side;
  cudaEvent_t ev_fork, ev_join;
  cudaStreamCreateWithFlags(&side, cudaStreamNonBlocking);
  cudaEventCreateWithFlags(&ev_fork, cudaEventDisableTiming);
  cudaEventCreateWithFlags(&ev_join, cudaEventDisableTiming);

  cudaEventRecord(ev_fork, 0);
  cudaStreamWaitEvent(side, ev_fork, 0);
  k_zero<<<(NN+255)/256, 256, 0, side>>>();
  k_hist<<<(NE+255)/256, 256, 0, side>>>(dst);
  k_scan<<<1, 1024, 0, side>>>();
  k_scatter<<<(NE+255)/256, 256, 0, side>>>(dst);
  cudaEventRecord(ev_join, side);

  // Main branch
  k_node<<<(NN+63)/64, 256, NODE_SMEM>>>(x, W_lin, b_lin,
      Wx0, Wh0, b0, Wx1, Wh1, b1);
  k_edge1<<<NE/128, 256, EDGE_SMEM>>>(ef0, ef1, src, dst,
      Wx0, Wh0, b0, Wx1, Wh1, b1, attn0, eta0, attn1, eta1, delta);

  cudaStreamWaitEvent(0, ev_join, 0);
  k_agg<<<(NN*32+255)/256, 256>>>(src, prob, out_mm, out_ms);
  k_out<<<(NN+63)/64, 256>>>(Wsrc, bsrc, Wedge, bedge, out);
  // Stream/events intentionally not destroyed (capture safety); replays
  // do not re-enter kernel_launch.
}